// round 12
// baseline (speedup 1.0000x reference)
#include <cuda_runtime.h>
#include <cstdint>

// Problem dims
#define T_STEPS 512
#define BATCH   64
#define INDIM   256
#define HID     512

// ---------------- f32x2 helpers (FFMA2 only reachable via PTX) ----------------
__device__ __forceinline__ unsigned long long pack2(float x, float y) {
    unsigned long long r;
    asm("mov.b64 %0, {%1,%2};" : "=l"(r) : "f"(x), "f"(y));
    return r;
}
__device__ __forceinline__ void unpack2(unsigned long long v, float& x, float& y) {
    asm("mov.b64 {%0,%1}, %2;" : "=f"(x), "=f"(y) : "l"(v));
}
__device__ __forceinline__ void fma2(unsigned long long& d, unsigned long long a,
                                     unsigned long long b) {
    asm("fma.rn.f32x2 %0, %1, %2, %0;" : "+l"(d) : "l"(a), "l"(b));
}

// ---------------- mbarrier / DSMEM helpers ----------------
__device__ __forceinline__ void mbar_init(unsigned addr, unsigned cnt) {
    asm volatile("mbarrier.init.shared.b64 [%0], %1;" :: "r"(addr), "r"(cnt) : "memory");
}
__device__ __forceinline__ void mbar_expect_tx(unsigned addr, unsigned bytes) {
    asm volatile("mbarrier.arrive.expect_tx.shared.b64 _, [%0], %1;"
                 :: "r"(addr), "r"(bytes) : "memory");
}
__device__ __forceinline__ void mbar_arrive_remote(unsigned addr) {
    asm volatile("mbarrier.arrive.release.cluster.shared::cluster.b64 _, [%0];"
                 :: "r"(addr) : "memory");
}
__device__ __forceinline__ void mbar_wait(unsigned addr, unsigned parity) {
    asm volatile(
        "{\n\t.reg .pred P;\n"
        "LW_%=:\n\t"
        "mbarrier.try_wait.parity.acquire.cluster.shared::cta.b64 P, [%0], %1, 0x989680;\n\t"
        "@P bra LD_%=;\n\t"
        "bra LW_%=;\n"
        "LD_%=:\n\t}"
        :: "r"(addr), "r"(parity) : "memory");
}
__device__ __forceinline__ void st_async64(unsigned daddr, unsigned long long v, unsigned mbar) {
    asm volatile("st.async.weak.shared::cluster.mbarrier::complete_tx::bytes.b64 [%0], %1, [%2];"
                 :: "r"(daddr), "l"(v), "r"(mbar) : "memory");
}
__device__ __forceinline__ unsigned mapa_sh(unsigned addr, unsigned rank) {
    unsigned r;
    asm("mapa.shared::cluster.u32 %0, %1, %2;" : "=r"(r) : "r"(addr), "r"(rank));
    return r;
}
#define CLUSTER_SYNC_ASM() do { \
    asm volatile("barrier.cluster.arrive.aligned;" ::: "memory"); \
    asm volatile("barrier.cluster.wait.aligned;" ::: "memory"); } while (0)

// ---------------- Phase 1: xw = x @ W_ih^T + bias_ih + bias_hh ----------------
__device__ float g_xw[(size_t)T_STEPS * BATCH * HID];   // 64 MB static scratch

#define BM 128
#define BN 128
#define BK 16
#define LDP 132

__global__ void __launch_bounds__(256, 2)
xw_gemm_kernel(const float* __restrict__ x, const float* __restrict__ wih,
               const float* __restrict__ bih, const float* __restrict__ bhh)
{
    __shared__ float As[BK * LDP];
    __shared__ float Bs[BK * LDP];

    const int tid = threadIdx.x;
    const int mb = blockIdx.x * BM;
    const int nb = blockIdx.y * BN;

    const int tx = tid & 15;
    const int ty = tid >> 4;
    const int m0 = ty * 8;
    const int n0 = tx * 8;

    const int lrow = tid >> 2;
    const int lk   = (tid & 3) * 4;

    unsigned long long acc2[4][8];
#pragma unroll
    for (int i = 0; i < 4; ++i)
#pragma unroll
        for (int n = 0; n < 8; ++n) acc2[i][n] = 0ull;

    for (int k0 = 0; k0 < INDIM; k0 += BK) {
#pragma unroll
        for (int h = 0; h < 2; ++h) {
            const int row = lrow + h * 64;
            float4 a = *reinterpret_cast<const float4*>(x + (size_t)(mb + row) * INDIM + k0 + lk);
            As[(lk + 0) * LDP + row] = a.x;
            As[(lk + 1) * LDP + row] = a.y;
            As[(lk + 2) * LDP + row] = a.z;
            As[(lk + 3) * LDP + row] = a.w;
            float4 b = *reinterpret_cast<const float4*>(wih + (size_t)(nb + row) * INDIM + k0 + lk);
            Bs[(lk + 0) * LDP + row] = b.x;
            Bs[(lk + 1) * LDP + row] = b.y;
            Bs[(lk + 2) * LDP + row] = b.z;
            Bs[(lk + 3) * LDP + row] = b.w;
        }
        __syncthreads();

#pragma unroll
        for (int k = 0; k < BK; ++k) {
            const ulonglong2* ap = reinterpret_cast<const ulonglong2*>(As + k * LDP + m0);
            ulonglong2 am0 = ap[0];
            ulonglong2 am1 = ap[1];
            unsigned long long av[4] = {am0.x, am0.y, am1.x, am1.y};
            float4 b0 = *reinterpret_cast<const float4*>(Bs + k * LDP + n0);
            float4 b1 = *reinterpret_cast<const float4*>(Bs + k * LDP + n0 + 4);
            unsigned long long bb[8] = {
                pack2(b0.x, b0.x), pack2(b0.y, b0.y), pack2(b0.z, b0.z), pack2(b0.w, b0.w),
                pack2(b1.x, b1.x), pack2(b1.y, b1.y), pack2(b1.z, b1.z), pack2(b1.w, b1.w)};
#pragma unroll
            for (int i = 0; i < 4; ++i)
#pragma unroll
                for (int n = 0; n < 8; ++n)
                    fma2(acc2[i][n], av[i], bb[n]);
        }
        __syncthreads();
    }

    float bia[8];
#pragma unroll
    for (int n = 0; n < 8; ++n)
        bia[n] = __ldg(bih + nb + n0 + n) + __ldg(bhh + nb + n0 + n);

#pragma unroll
    for (int i = 0; i < 4; ++i) {
        float lo[8], hi[8];
#pragma unroll
        for (int n = 0; n < 8; ++n) unpack2(acc2[i][n], lo[n], hi[n]);
        float* dst0 = g_xw + (size_t)(mb + m0 + 2 * i) * HID + nb + n0;
        float* dst1 = dst0 + HID;
        float4 o;
        o.x = lo[0] + bia[0]; o.y = lo[1] + bia[1]; o.z = lo[2] + bia[2]; o.w = lo[3] + bia[3];
        *reinterpret_cast<float4*>(dst0) = o;
        o.x = lo[4] + bia[4]; o.y = lo[5] + bia[5]; o.z = lo[6] + bia[6]; o.w = lo[7] + bia[7];
        *reinterpret_cast<float4*>(dst0 + 4) = o;
        o.x = hi[0] + bia[0]; o.y = hi[1] + bia[1]; o.z = hi[2] + bia[2]; o.w = hi[3] + bia[3];
        *reinterpret_cast<float4*>(dst1) = o;
        o.x = hi[4] + bia[4]; o.y = hi[5] + bia[5]; o.z = hi[6] + bia[6]; o.w = hi[7] + bia[7];
        *reinterpret_cast<float4*>(dst1 + 4) = o;
    }
}

// ---------------- Phase 2: recurrence ----------------
// 16 clusters x 8 CTAs, 512 threads/CTA (kp = tid>>6 in 0..7, j = tid&63).
// CTA rank r owns j in [r*64, r*64+64); W slice in registers (32 u64/thread).
// h exchange: st.async 16B chunks into every peer's double-buffered hb, tracked by
// per-buffer FULL mbarriers (tx-count 8192B). WAR via per-buffer EMPTY mbarriers
// (count 8: every CTA release-arrives on every peer after finishing its reads).

#define CL_SIZE     8
#define RNN_THREADS 512
#define RNN_CTAS    128          // 16 clusters * 8

__global__ void __launch_bounds__(RNN_THREADS, 1) __cluster_dims__(CL_SIZE, 1, 1)
rnn_kernel(const float* __restrict__ whh, float* __restrict__ out)
{
    __shared__ alignas(16) float hb[2][4][HID];     // 16KB double-buffered h
    __shared__ alignas(16) float red[8][4][64];     // 8KB  k-partials
    __shared__ alignas(16) float stage[4][64];      // 1KB  scatter staging
    __shared__ alignas(8)  unsigned long long mbar[4];  // full0,full1,empty0,empty1

    const int tid  = threadIdx.x;
    const int rank = blockIdx.x & (CL_SIZE - 1);
    const int cl   = blockIdx.x >> 3;
    const int j0   = rank * 64;
    const int b0   = cl * 4;
    const int kp   = tid >> 6;      // 0..7
    const int j    = tid & 63;
    const int jg   = j0 + j;

    // W_hh[jg][kp*64 .. kp*64+64) -> 32 packed u64 (k-pairs)
    unsigned long long w2[32];
    {
        const unsigned long long* wrow =
            reinterpret_cast<const unsigned long long*>(whh + (size_t)jg * HID + kp * 64);
#pragma unroll
        for (int i = 0; i < 32; ++i) w2[i] = wrow[i];
    }

    // zero t=0 read buffer
    for (int i = tid; i < 4 * HID; i += RNN_THREADS) (&hb[1][0][0])[i] = 0.f;

    const unsigned mbarL = (unsigned)__cvta_generic_to_shared(mbar);
    const unsigned hbL   = (unsigned)__cvta_generic_to_shared(&hb[0][0][0]);

    if (tid == 0) {
        mbar_init(mbarL + 0,  1);    // full0  (1 arrive via expect_tx + 8192B tx)
        mbar_init(mbarL + 8,  1);    // full1
        mbar_init(mbarL + 16, 8);    // empty0 (8 consumer arrives)
        mbar_init(mbarL + 24, 8);    // empty1
        mbar_expect_tx(mbarL + 0, 8192);   // expect for t=0 fill of buffer 0
    }

    // per-thread remote targets: scatter destination = rank kp
    const unsigned remHbK = mapa_sh(hbL,   (unsigned)kp);
    const unsigned remMbK = mapa_sh(mbarL, (unsigned)kp);
    // for empty broadcast (threads 0..7 -> peer tid)
    const unsigned remMbE = mapa_sh(mbarL, (unsigned)(tid & 7));

    float xw = (tid < 256) ? g_xw[(size_t)(b0 + kp) * HID + jg] : 0.f;

    __syncthreads();
    CLUSTER_SYNC_ASM();   // mbarrier inits visible cluster-wide

    int pf0 = 0, pf1 = 0, pe0 = 0, pe1 = 0;

    for (int t = 0; t < T_STEPS; ++t) {
        const int rb = (t + 1) & 1;   // holds h_{t-1}
        const int wb = t & 1;         // receives h_t

        if (t > 0) {   // wait until hb[rb] fully delivered (tx-complete, acquire)
            mbar_wait(mbarL + rb * 8, rb ? pf1 : pf0);
            if (rb) pf1 ^= 1; else pf0 ^= 1;
        }
        // post expect for rb's NEXT fill (step t+1) BEFORE releasing producers
        if (tid == 0 && t < T_STEPS - 1) mbar_expect_tx(mbarL + rb * 8, 8192);

        // ---- GEMV: k in [kp*64, kp*64+64), 4 batches, f32x2 along k ----
        unsigned long long a0 = 0, a1 = 0, a2 = 0, a3 = 0;
        const ulonglong2* p0 = reinterpret_cast<const ulonglong2*>(&hb[rb][0][kp * 64]);
        const ulonglong2* p1 = reinterpret_cast<const ulonglong2*>(&hb[rb][1][kp * 64]);
        const ulonglong2* p2 = reinterpret_cast<const ulonglong2*>(&hb[rb][2][kp * 64]);
        const ulonglong2* p3 = reinterpret_cast<const ulonglong2*>(&hb[rb][3][kp * 64]);
#pragma unroll
        for (int q = 0; q < 16; ++q) {
            ulonglong2 v0 = p0[q], v1 = p1[q], v2 = p2[q], v3 = p3[q];
            fma2(a0, w2[2 * q], v0.x); fma2(a0, w2[2 * q + 1], v0.y);
            fma2(a1, w2[2 * q], v1.x); fma2(a1, w2[2 * q + 1], v1.y);
            fma2(a2, w2[2 * q], v2.x); fma2(a2, w2[2 * q + 1], v2.y);
            fma2(a3, w2[2 * q], v3.x); fma2(a3, w2[2 * q + 1], v3.y);
        }
        {
            float x0, y0, x1, y1, x2, y2, x3, y3;
            unpack2(a0, x0, y0); unpack2(a1, x1, y1);
            unpack2(a2, x2, y2); unpack2(a3, x3, y3);
            red[kp][0][j] = x0 + y0;
            red[kp][1][j] = x1 + y1;
            red[kp][2][j] = x2 + y2;
            red[kp][3][j] = x3 + y3;
        }
        // prefetch next xw (independent of sync below)
        float nxw = xw;
        if (tid < 256 && t + 1 < T_STEPS)
            nxw = g_xw[((size_t)(t + 1) * BATCH + b0 + kp) * HID + jg];

        __syncthreads();   // all reads of hb[rb] + red writes complete

        // broadcast "hb[rb] consumed" to all 8 CTAs (release)
        if (tid < 8 && t < T_STEPS - 1)
            mbar_arrive_remote(remMbE + 16 + rb * 8);

        // ---- finalize (batch kp<4, column jg) ----
        float v = 0.f;
        if (tid < 256) {
            float s = red[0][kp][j] + red[1][kp][j] + red[2][kp][j] + red[3][kp][j]
                    + red[4][kp][j] + red[5][kp][j] + red[6][kp][j] + red[7][kp][j];
            v = fmaxf(xw + s, 0.f);
            out[((size_t)t * BATCH + b0 + kp) * HID + jg] = v;
        }

        if (t == T_STEPS - 1) {
            if (tid < 256)
                out[(size_t)T_STEPS * BATCH * HID + (size_t)(b0 + kp) * HID + jg] = v;
        } else {
            if (tid < 256) stage[kp][j] = v;
            __syncthreads();

            // WAR: all 8 consumers must have finished reading buffer wb (step t-1)
            if (t > 0) {
                mbar_wait(mbarL + 16 + wb * 8, wb ? pe1 : pe0);
                if (wb) pe1 ^= 1; else pe0 ^= 1;
            }

            // scatter: thread (kp, j) sends chunk j of the 1KB slice to peer kp.
            // chunk j -> batch b = j>>4, j-quad jq = j&15 (16B)
            {
                const int b  = j >> 4;
                const int jq = j & 15;
                const ulonglong2 val = *reinterpret_cast<const ulonglong2*>(&stage[b][jq * 4]);
                const unsigned dst = remHbK + (unsigned)(((wb * 4 + b) * HID + j0 + jq * 4) << 2);
                const unsigned fm  = remMbK + wb * 8;
                st_async64(dst,     val.x, fm);
                st_async64(dst + 8, val.y, fm);
            }
            xw = nxw;
        }
    }
    // no CTA exits while peers' async ops may target its smem
    CLUSTER_SYNC_ASM();
}

// ---------------- launch ----------------
extern "C" void kernel_launch(void* const* d_in, const int* in_sizes, int n_in,
                              void* d_out, int out_size)
{
    (void)in_sizes; (void)n_in; (void)out_size;
    const float* x   = (const float*)d_in[0];
    const float* wih = (const float*)d_in[1];
    const float* whh = (const float*)d_in[2];
    const float* bih = (const float*)d_in[3];
    const float* bhh = (const float*)d_in[4];
    float* out = (float*)d_out;

    dim3 g1((T_STEPS * BATCH) / BM, HID / BN);   // (256, 4)
    xw_gemm_kernel<<<g1, 256>>>(x, wih, bih, bhh);

    rnn_kernel<<<RNN_CTAS, RNN_THREADS>>>(whh, out);   // 128 CTAs, 16 clusters
}

// round 13
// speedup vs baseline: 1.0072x; 1.0072x over previous
#include <cuda_runtime.h>
#include <cstdint>

// Problem dims
#define T_STEPS 512
#define BATCH   64
#define INDIM   256
#define HID     512

// ---------------- f32x2 helpers (FFMA2 only reachable via PTX) ----------------
__device__ __forceinline__ unsigned long long pack2(float x, float y) {
    unsigned long long r;
    asm("mov.b64 %0, {%1,%2};" : "=l"(r) : "f"(x), "f"(y));
    return r;
}
__device__ __forceinline__ void unpack2(unsigned long long v, float& x, float& y) {
    asm("mov.b64 {%0,%1}, %2;" : "=f"(x), "=f"(y) : "l"(v));
}
__device__ __forceinline__ void fma2(unsigned long long& d, unsigned long long a,
                                     unsigned long long b) {
    asm("fma.rn.f32x2 %0, %1, %2, %0;" : "+l"(d) : "l"(a), "l"(b));
}

// ---------------- mbarrier / DSMEM helpers ----------------
__device__ __forceinline__ void mbar_init(unsigned addr, unsigned cnt) {
    asm volatile("mbarrier.init.shared.b64 [%0], %1;" :: "r"(addr), "r"(cnt) : "memory");
}
__device__ __forceinline__ void mbar_expect_tx(unsigned addr, unsigned bytes) {
    asm volatile("mbarrier.arrive.expect_tx.shared.b64 _, [%0], %1;"
                 :: "r"(addr), "r"(bytes) : "memory");
}
__device__ __forceinline__ void mbar_arrive_remote(unsigned addr) {
    asm volatile("mbarrier.arrive.release.cluster.shared::cluster.b64 _, [%0];"
                 :: "r"(addr) : "memory");
}
__device__ __forceinline__ void mbar_wait(unsigned addr, unsigned parity) {
    asm volatile(
        "{\n\t.reg .pred P;\n"
        "LW_%=:\n\t"
        "mbarrier.try_wait.parity.acquire.cluster.shared::cta.b64 P, [%0], %1, 0x989680;\n\t"
        "@P bra LD_%=;\n\t"
        "bra LW_%=;\n"
        "LD_%=:\n\t}"
        :: "r"(addr), "r"(parity) : "memory");
}
__device__ __forceinline__ void st_async64(unsigned daddr, unsigned long long v, unsigned mbar) {
    asm volatile("st.async.weak.shared::cluster.mbarrier::complete_tx::bytes.b64 [%0], %1, [%2];"
                 :: "r"(daddr), "l"(v), "r"(mbar) : "memory");
}
__device__ __forceinline__ unsigned mapa_sh(unsigned addr, unsigned rank) {
    unsigned r;
    asm("mapa.shared::cluster.u32 %0, %1, %2;" : "=r"(r) : "r"(addr), "r"(rank));
    return r;
}
#define CLUSTER_SYNC_ASM() do { \
    asm volatile("barrier.cluster.arrive.aligned;" ::: "memory"); \
    asm volatile("barrier.cluster.wait.aligned;" ::: "memory"); } while (0)

// ---------------- Phase 1: xw = x @ W_ih^T + bias_ih + bias_hh ----------------
__device__ float g_xw[(size_t)T_STEPS * BATCH * HID];   // 64 MB static scratch

#define BM 128
#define BN 128
#define BK 16
#define LDP 132

__global__ void __launch_bounds__(256, 2)
xw_gemm_kernel(const float* __restrict__ x, const float* __restrict__ wih,
               const float* __restrict__ bih, const float* __restrict__ bhh)
{
    __shared__ float As[BK * LDP];
    __shared__ float Bs[BK * LDP];

    const int tid = threadIdx.x;
    const int mb = blockIdx.x * BM;
    const int nb = blockIdx.y * BN;

    const int tx = tid & 15;
    const int ty = tid >> 4;
    const int m0 = ty * 8;
    const int n0 = tx * 8;

    const int lrow = tid >> 2;
    const int lk   = (tid & 3) * 4;

    unsigned long long acc2[4][8];
#pragma unroll
    for (int i = 0; i < 4; ++i)
#pragma unroll
        for (int n = 0; n < 8; ++n) acc2[i][n] = 0ull;

    for (int k0 = 0; k0 < INDIM; k0 += BK) {
#pragma unroll
        for (int h = 0; h < 2; ++h) {
            const int row = lrow + h * 64;
            float4 a = *reinterpret_cast<const float4*>(x + (size_t)(mb + row) * INDIM + k0 + lk);
            As[(lk + 0) * LDP + row] = a.x;
            As[(lk + 1) * LDP + row] = a.y;
            As[(lk + 2) * LDP + row] = a.z;
            As[(lk + 3) * LDP + row] = a.w;
            float4 b = *reinterpret_cast<const float4*>(wih + (size_t)(nb + row) * INDIM + k0 + lk);
            Bs[(lk + 0) * LDP + row] = b.x;
            Bs[(lk + 1) * LDP + row] = b.y;
            Bs[(lk + 2) * LDP + row] = b.z;
            Bs[(lk + 3) * LDP + row] = b.w;
        }
        __syncthreads();

#pragma unroll
        for (int k = 0; k < BK; ++k) {
            const ulonglong2* ap = reinterpret_cast<const ulonglong2*>(As + k * LDP + m0);
            ulonglong2 am0 = ap[0];
            ulonglong2 am1 = ap[1];
            unsigned long long av[4] = {am0.x, am0.y, am1.x, am1.y};
            float4 b0 = *reinterpret_cast<const float4*>(Bs + k * LDP + n0);
            float4 b1 = *reinterpret_cast<const float4*>(Bs + k * LDP + n0 + 4);
            unsigned long long bb[8] = {
                pack2(b0.x, b0.x), pack2(b0.y, b0.y), pack2(b0.z, b0.z), pack2(b0.w, b0.w),
                pack2(b1.x, b1.x), pack2(b1.y, b1.y), pack2(b1.z, b1.z), pack2(b1.w, b1.w)};
#pragma unroll
            for (int i = 0; i < 4; ++i)
#pragma unroll
                for (int n = 0; n < 8; ++n)
                    fma2(acc2[i][n], av[i], bb[n]);
        }
        __syncthreads();
    }

    float bia[8];
#pragma unroll
    for (int n = 0; n < 8; ++n)
        bia[n] = __ldg(bih + nb + n0 + n) + __ldg(bhh + nb + n0 + n);

#pragma unroll
    for (int i = 0; i < 4; ++i) {
        float lo[8], hi[8];
#pragma unroll
        for (int n = 0; n < 8; ++n) unpack2(acc2[i][n], lo[n], hi[n]);
        float* dst0 = g_xw + (size_t)(mb + m0 + 2 * i) * HID + nb + n0;
        float* dst1 = dst0 + HID;
        float4 o;
        o.x = lo[0] + bia[0]; o.y = lo[1] + bia[1]; o.z = lo[2] + bia[2]; o.w = lo[3] + bia[3];
        *reinterpret_cast<float4*>(dst0) = o;
        o.x = lo[4] + bia[4]; o.y = lo[5] + bia[5]; o.z = lo[6] + bia[6]; o.w = lo[7] + bia[7];
        *reinterpret_cast<float4*>(dst0 + 4) = o;
        o.x = hi[0] + bia[0]; o.y = hi[1] + bia[1]; o.z = hi[2] + bia[2]; o.w = hi[3] + bia[3];
        *reinterpret_cast<float4*>(dst1) = o;
        o.x = hi[4] + bia[4]; o.y = hi[5] + bia[5]; o.z = hi[6] + bia[6]; o.w = hi[7] + bia[7];
        *reinterpret_cast<float4*>(dst1 + 4) = o;
    }
}

// ---------------- Phase 2: recurrence ----------------
// 16 clusters x 8 CTAs, 512 threads/CTA (kp = tid>>6 in 0..7, j = tid&63).
// CTA rank r owns j in [r*64, r*64+64); W slice in registers (32 u64/thread).
// h exchange: st.async 16B chunks into every peer's double-buffered hb, tracked by
// per-buffer FULL mbarriers (tx-count 8192B). WAR via per-buffer EMPTY mbarriers
// (count 8: every CTA release-arrives on every peer after finishing its reads).

#define CL_SIZE     8
#define RNN_THREADS 512
#define RNN_CTAS    128          // 16 clusters * 8

__global__ void __launch_bounds__(RNN_THREADS, 1) __cluster_dims__(CL_SIZE, 1, 1)
rnn_kernel(const float* __restrict__ whh, float* __restrict__ out)
{
    __shared__ alignas(16) float hb[2][4][HID];     // 16KB double-buffered h
    __shared__ alignas(16) float red[8][4][64];     // 8KB  k-partials
    __shared__ alignas(16) float stage[4][64];      // 1KB  scatter staging
    __shared__ alignas(8)  unsigned long long mbar[4];  // full0,full1,empty0,empty1

    const int tid  = threadIdx.x;
    const int rank = blockIdx.x & (CL_SIZE - 1);
    const int cl   = blockIdx.x >> 3;
    const int j0   = rank * 64;
    const int b0   = cl * 4;
    const int kp   = tid >> 6;      // 0..7
    const int j    = tid & 63;
    const int jg   = j0 + j;

    // W_hh[jg][kp*64 .. kp*64+64) -> 32 packed u64 (k-pairs)
    unsigned long long w2[32];
    {
        const unsigned long long* wrow =
            reinterpret_cast<const unsigned long long*>(whh + (size_t)jg * HID + kp * 64);
#pragma unroll
        for (int i = 0; i < 32; ++i) w2[i] = wrow[i];
    }

    // zero t=0 read buffer
    for (int i = tid; i < 4 * HID; i += RNN_THREADS) (&hb[1][0][0])[i] = 0.f;

    const unsigned mbarL = (unsigned)__cvta_generic_to_shared(mbar);
    const unsigned hbL   = (unsigned)__cvta_generic_to_shared(&hb[0][0][0]);

    if (tid == 0) {
        mbar_init(mbarL + 0,  1);    // full0  (1 arrive via expect_tx + 8192B tx)
        mbar_init(mbarL + 8,  1);    // full1
        mbar_init(mbarL + 16, 8);    // empty0 (8 consumer arrives)
        mbar_init(mbarL + 24, 8);    // empty1
        mbar_expect_tx(mbarL + 0, 8192);   // expect for t=0 fill of buffer 0
    }

    // per-thread remote targets: scatter destination = rank kp
    const unsigned remHbK = mapa_sh(hbL,   (unsigned)kp);
    const unsigned remMbK = mapa_sh(mbarL, (unsigned)kp);
    // for empty broadcast (threads 0..7 -> peer tid)
    const unsigned remMbE = mapa_sh(mbarL, (unsigned)(tid & 7));

    float xw = (tid < 256) ? g_xw[(size_t)(b0 + kp) * HID + jg] : 0.f;

    __syncthreads();
    CLUSTER_SYNC_ASM();   // mbarrier inits visible cluster-wide

    int pf0 = 0, pf1 = 0, pe0 = 0, pe1 = 0;

    for (int t = 0; t < T_STEPS; ++t) {
        const int rb = (t + 1) & 1;   // holds h_{t-1}
        const int wb = t & 1;         // receives h_t

        if (t > 0) {   // wait until hb[rb] fully delivered (tx-complete, acquire)
            mbar_wait(mbarL + rb * 8, rb ? pf1 : pf0);
            if (rb) pf1 ^= 1; else pf0 ^= 1;
        }
        // post expect for rb's NEXT fill (step t+1) BEFORE releasing producers
        if (tid == 0 && t < T_STEPS - 1) mbar_expect_tx(mbarL + rb * 8, 8192);

        // ---- GEMV: k in [kp*64, kp*64+64), 4 batches, f32x2 along k ----
        unsigned long long a0 = 0, a1 = 0, a2 = 0, a3 = 0;
        const ulonglong2* p0 = reinterpret_cast<const ulonglong2*>(&hb[rb][0][kp * 64]);
        const ulonglong2* p1 = reinterpret_cast<const ulonglong2*>(&hb[rb][1][kp * 64]);
        const ulonglong2* p2 = reinterpret_cast<const ulonglong2*>(&hb[rb][2][kp * 64]);
        const ulonglong2* p3 = reinterpret_cast<const ulonglong2*>(&hb[rb][3][kp * 64]);
#pragma unroll
        for (int q = 0; q < 16; ++q) {
            ulonglong2 v0 = p0[q], v1 = p1[q], v2 = p2[q], v3 = p3[q];
            fma2(a0, w2[2 * q], v0.x); fma2(a0, w2[2 * q + 1], v0.y);
            fma2(a1, w2[2 * q], v1.x); fma2(a1, w2[2 * q + 1], v1.y);
            fma2(a2, w2[2 * q], v2.x); fma2(a2, w2[2 * q + 1], v2.y);
            fma2(a3, w2[2 * q], v3.x); fma2(a3, w2[2 * q + 1], v3.y);
        }
        {
            float x0, y0, x1, y1, x2, y2, x3, y3;
            unpack2(a0, x0, y0); unpack2(a1, x1, y1);
            unpack2(a2, x2, y2); unpack2(a3, x3, y3);
            red[kp][0][j] = x0 + y0;
            red[kp][1][j] = x1 + y1;
            red[kp][2][j] = x2 + y2;
            red[kp][3][j] = x3 + y3;
        }
        // prefetch next xw (independent of sync below)
        float nxw = xw;
        if (tid < 256 && t + 1 < T_STEPS)
            nxw = g_xw[((size_t)(t + 1) * BATCH + b0 + kp) * HID + jg];

        __syncthreads();   // all reads of hb[rb] + red writes complete

        // broadcast "hb[rb] consumed" to all 8 CTAs (release)
        if (tid < 8 && t < T_STEPS - 1)
            mbar_arrive_remote(remMbE + 16 + rb * 8);

        // ---- finalize (batch kp<4, column jg) ----
        float v = 0.f;
        if (tid < 256) {
            float s = red[0][kp][j] + red[1][kp][j] + red[2][kp][j] + red[3][kp][j]
                    + red[4][kp][j] + red[5][kp][j] + red[6][kp][j] + red[7][kp][j];
            v = fmaxf(xw + s, 0.f);
            out[((size_t)t * BATCH + b0 + kp) * HID + jg] = v;
        }

        if (t == T_STEPS - 1) {
            if (tid < 256)
                out[(size_t)T_STEPS * BATCH * HID + (size_t)(b0 + kp) * HID + jg] = v;
        } else {
            if (tid < 256) stage[kp][j] = v;
            __syncthreads();

            // WAR: all 8 consumers must have finished reading buffer wb (step t-1)
            if (t > 0) {
                mbar_wait(mbarL + 16 + wb * 8, wb ? pe1 : pe0);
                if (wb) pe1 ^= 1; else pe0 ^= 1;
            }

            // scatter: thread (kp, j) sends chunk j of the 1KB slice to peer kp.
            // chunk j -> batch b = j>>4, j-quad jq = j&15 (16B)
            {
                const int b  = j >> 4;
                const int jq = j & 15;
                const ulonglong2 val = *reinterpret_cast<const ulonglong2*>(&stage[b][jq * 4]);
                const unsigned dst = remHbK + (unsigned)(((wb * 4 + b) * HID + j0 + jq * 4) << 2);
                const unsigned fm  = remMbK + wb * 8;
                st_async64(dst,     val.x, fm);
                st_async64(dst + 8, val.y, fm);
            }
            xw = nxw;
        }
    }
    // no CTA exits while peers' async ops may target its smem
    CLUSTER_SYNC_ASM();
}

// ---------------- launch ----------------
extern "C" void kernel_launch(void* const* d_in, const int* in_sizes, int n_in,
                              void* d_out, int out_size)
{
    (void)in_sizes; (void)n_in; (void)out_size;
    const float* x   = (const float*)d_in[0];
    const float* wih = (const float*)d_in[1];
    const float* whh = (const float*)d_in[2];
    const float* bih = (const float*)d_in[3];
    const float* bhh = (const float*)d_in[4];
    float* out = (float*)d_out;

    dim3 g1((T_STEPS * BATCH) / BM, HID / BN);   // (256, 4)
    xw_gemm_kernel<<<g1, 256>>>(x, wih, bih, bhh);

    rnn_kernel<<<RNN_CTAS, RNN_THREADS>>>(whh, out);   // 128 CTAs, 16 clusters
}

// round 14
// speedup vs baseline: 1.6262x; 1.6146x over previous
#include <cuda_runtime.h>
#include <cstdint>

// Problem dims
#define T_STEPS 512
#define BATCH   64
#define INDIM   256
#define HID     512

// ---------------- f32x2 helpers (FFMA2 only reachable via PTX) ----------------
__device__ __forceinline__ unsigned long long pack2(float x, float y) {
    unsigned long long r;
    asm("mov.b64 %0, {%1,%2};" : "=l"(r) : "f"(x), "f"(y));
    return r;
}
__device__ __forceinline__ void unpack2(unsigned long long v, float& x, float& y) {
    asm("mov.b64 {%0,%1}, %2;" : "=f"(x), "=f"(y) : "l"(v));
}
__device__ __forceinline__ void fma2(unsigned long long& d, unsigned long long a,
                                     unsigned long long b) {
    asm("fma.rn.f32x2 %0, %1, %2, %0;" : "+l"(d) : "l"(a), "l"(b));
}

// ---------------- mbarrier / DSMEM helpers ----------------
__device__ __forceinline__ void mbar_init(unsigned addr, unsigned cnt) {
    asm volatile("mbarrier.init.shared.b64 [%0], %1;" :: "r"(addr), "r"(cnt) : "memory");
}
__device__ __forceinline__ void mbar_expect_tx(unsigned addr, unsigned bytes) {
    asm volatile("mbarrier.arrive.expect_tx.shared.b64 _, [%0], %1;"
                 :: "r"(addr), "r"(bytes) : "memory");
}
__device__ __forceinline__ void mbar_wait(unsigned addr, unsigned parity) {
    asm volatile(
        "{\n\t.reg .pred P;\n"
        "LW_%=:\n\t"
        "mbarrier.try_wait.parity.acquire.cluster.shared::cta.b64 P, [%0], %1, 0x989680;\n\t"
        "@P bra LD_%=;\n\t"
        "bra LW_%=;\n"
        "LD_%=:\n\t}"
        :: "r"(addr), "r"(parity) : "memory");
}
__device__ __forceinline__ unsigned mapa_sh(unsigned addr, unsigned rank) {
    unsigned r;
    asm("mapa.shared::cluster.u32 %0, %1, %2;" : "=r"(r) : "r"(addr), "r"(rank));
    return r;
}
// 1KB bulk DSMEM copy with tx-accounting into the DESTINATION CTA's mbarrier
__device__ __forceinline__ void bulk_dsmem(unsigned dst, unsigned src, unsigned bytes,
                                           unsigned dst_mbar) {
    asm volatile(
        "cp.async.bulk.shared::cluster.shared::cta.mbarrier::complete_tx::bytes "
        "[%0], [%1], %2, [%3];"
        :: "r"(dst), "r"(src), "r"(bytes), "r"(dst_mbar) : "memory");
}
#define CLUSTER_SYNC_ASM() do { \
    asm volatile("barrier.cluster.arrive.aligned;" ::: "memory"); \
    asm volatile("barrier.cluster.wait.aligned;" ::: "memory"); } while (0)

// ---------------- Phase 1: xw = x @ W_ih^T + bias_ih + bias_hh ----------------
__device__ float g_xw[(size_t)T_STEPS * BATCH * HID];   // 64 MB static scratch

#define BM 128
#define BN 128
#define BK 16
#define LDP 132

__global__ void __launch_bounds__(256, 2)
xw_gemm_kernel(const float* __restrict__ x, const float* __restrict__ wih,
               const float* __restrict__ bih, const float* __restrict__ bhh)
{
    __shared__ float As[BK * LDP];
    __shared__ float Bs[BK * LDP];

    const int tid = threadIdx.x;
    const int mb = blockIdx.x * BM;
    const int nb = blockIdx.y * BN;

    const int tx = tid & 15;
    const int ty = tid >> 4;
    const int m0 = ty * 8;
    const int n0 = tx * 8;

    const int lrow = tid >> 2;
    const int lk   = (tid & 3) * 4;

    unsigned long long acc2[4][8];
#pragma unroll
    for (int i = 0; i < 4; ++i)
#pragma unroll
        for (int n = 0; n < 8; ++n) acc2[i][n] = 0ull;

    for (int k0 = 0; k0 < INDIM; k0 += BK) {
#pragma unroll
        for (int h = 0; h < 2; ++h) {
            const int row = lrow + h * 64;
            float4 a = *reinterpret_cast<const float4*>(x + (size_t)(mb + row) * INDIM + k0 + lk);
            As[(lk + 0) * LDP + row] = a.x;
            As[(lk + 1) * LDP + row] = a.y;
            As[(lk + 2) * LDP + row] = a.z;
            As[(lk + 3) * LDP + row] = a.w;
            float4 b = *reinterpret_cast<const float4*>(wih + (size_t)(nb + row) * INDIM + k0 + lk);
            Bs[(lk + 0) * LDP + row] = b.x;
            Bs[(lk + 1) * LDP + row] = b.y;
            Bs[(lk + 2) * LDP + row] = b.z;
            Bs[(lk + 3) * LDP + row] = b.w;
        }
        __syncthreads();

#pragma unroll
        for (int k = 0; k < BK; ++k) {
            const ulonglong2* ap = reinterpret_cast<const ulonglong2*>(As + k * LDP + m0);
            ulonglong2 am0 = ap[0];
            ulonglong2 am1 = ap[1];
            unsigned long long av[4] = {am0.x, am0.y, am1.x, am1.y};
            float4 b0 = *reinterpret_cast<const float4*>(Bs + k * LDP + n0);
            float4 b1 = *reinterpret_cast<const float4*>(Bs + k * LDP + n0 + 4);
            unsigned long long bb[8] = {
                pack2(b0.x, b0.x), pack2(b0.y, b0.y), pack2(b0.z, b0.z), pack2(b0.w, b0.w),
                pack2(b1.x, b1.x), pack2(b1.y, b1.y), pack2(b1.z, b1.z), pack2(b1.w, b1.w)};
#pragma unroll
            for (int i = 0; i < 4; ++i)
#pragma unroll
                for (int n = 0; n < 8; ++n)
                    fma2(acc2[i][n], av[i], bb[n]);
        }
        __syncthreads();
    }

    float bia[8];
#pragma unroll
    for (int n = 0; n < 8; ++n)
        bia[n] = __ldg(bih + nb + n0 + n) + __ldg(bhh + nb + n0 + n);

#pragma unroll
    for (int i = 0; i < 4; ++i) {
        float lo[8], hi[8];
#pragma unroll
        for (int n = 0; n < 8; ++n) unpack2(acc2[i][n], lo[n], hi[n]);
        float* dst0 = g_xw + (size_t)(mb + m0 + 2 * i) * HID + nb + n0;
        float* dst1 = dst0 + HID;
        float4 o;
        o.x = lo[0] + bia[0]; o.y = lo[1] + bia[1]; o.z = lo[2] + bia[2]; o.w = lo[3] + bia[3];
        *reinterpret_cast<float4*>(dst0) = o;
        o.x = lo[4] + bia[4]; o.y = lo[5] + bia[5]; o.z = lo[6] + bia[6]; o.w = lo[7] + bia[7];
        *reinterpret_cast<float4*>(dst0 + 4) = o;
        o.x = hi[0] + bia[0]; o.y = hi[1] + bia[1]; o.z = hi[2] + bia[2]; o.w = hi[3] + bia[3];
        *reinterpret_cast<float4*>(dst1) = o;
        o.x = hi[4] + bia[4]; o.y = hi[5] + bia[5]; o.z = hi[6] + bia[6]; o.w = hi[7] + bia[7];
        *reinterpret_cast<float4*>(dst1 + 4) = o;
    }
}

// ---------------- Phase 2: recurrence (k-partitioned reduce-scatter) ----------------
// 16 clusters x 8 CTAs, 512 threads. Cluster = 4 batches.
// CTA rank r owns k-slice AND j-slice [64r, 64r+64).
//   GEMV:  thread j (=tid, all 512 j) computes partial[j,b] = sum_{k in Kr} W[j,k] h[b,k]
//          from LOCAL hcur (the slice this CTA finalized last step). W in regs (32 u64).
//   Exchange: partials for j in Jp -> ONE cp.async.bulk (1KB) to CTA p's recvbuf,
//          tx-counted into p's full[wb] mbarrier (expects 8 x 1KB).
//   Finalize: after mbar wait, tid<256 sums 8 partials, relu(+xw), writes out + hcur.
// Double buffering + the 2-step data dependency chain gives WAR ordering: no empty
// barrier, no per-step cluster.sync.

#define CL_SIZE     8
#define RNN_THREADS 512
#define RNN_CTAS    128          // 16 clusters * 8

__global__ void __launch_bounds__(RNN_THREADS, 1) __cluster_dims__(CL_SIZE, 1, 1)
rnn_kernel(const float* __restrict__ whh, float* __restrict__ out)
{
    __shared__ alignas(16) float hcur[4][64];           // 1KB  local h slice (k in Kr)
    __shared__ alignas(16) float stage[CL_SIZE][4][64]; // 8KB  outgoing partials per peer
    __shared__ alignas(16) float recv[2][CL_SIZE][4][64]; // 16KB incoming partials (dbl buf)
    __shared__ alignas(8)  unsigned long long mbar[2];  // full[0], full[1]

    const int tid  = threadIdx.x;
    const int rank = blockIdx.x & (CL_SIZE - 1);
    const int cl   = blockIdx.x >> 3;
    const int b0   = cl * 4;
    const int jg   = tid;            // global j this thread computes partials for
    const int kb   = rank * 64;      // our k-slice base

    // W_hh[jg][kb .. kb+64) -> 32 packed u64 (k-pairs), register-resident
    unsigned long long w2[32];
    {
        const unsigned long long* wrow =
            reinterpret_cast<const unsigned long long*>(whh + (size_t)jg * HID + kb);
#pragma unroll
        for (int i = 0; i < 32; ++i) w2[i] = wrow[i];
    }

    // h(-1) = 0
    if (tid < 256) (&hcur[0][0])[tid] = 0.f;

    const unsigned mbarL  = (unsigned)__cvta_generic_to_shared(mbar);
    const unsigned recvL  = (unsigned)__cvta_generic_to_shared(&recv[0][0][0][0]);
    const unsigned stageL = (unsigned)__cvta_generic_to_shared(&stage[0][0][0]);

    if (tid == 0) {
        mbar_init(mbarL + 0, 1);
        mbar_init(mbarL + 8, 1);
        mbar_expect_tx(mbarL + 0, 8192);   // phase for step 0
        mbar_expect_tx(mbarL + 8, 8192);   // phase for step 1
    }

    // per-thread remote targets (threads 0..7 are the bulk issuers, peer = tid)
    const unsigned peer      = (unsigned)(tid & 7);
    const unsigned remRecv   = mapa_sh(recvL, peer);    // base of peer's recv[0]
    const unsigned remMbar   = mapa_sh(mbarL, peer);
    const unsigned mySlotOff = (unsigned)(rank * 1024); // my 1KB slot in peer's recv[wb]

    // finalize-thread indices (tid < 256): batch b, local j = kj
    const int fb  = tid >> 6;        // 0..3
    const int fkj = tid & 63;        // 0..63
    float xw = (tid < 256) ? g_xw[(size_t)(b0 + fb) * HID + kb + fkj] : 0.f;

    __syncthreads();
    CLUSTER_SYNC_ASM();   // mbarrier inits + expects visible cluster-wide

    int par[2] = {0, 0};

    for (int t = 0; t < T_STEPS; ++t) {
        const int wb = t & 1;

        // ---- GEMV: partial[jg, b] over k in [kb, kb+64), from LOCAL hcur ----
        unsigned long long a0 = 0, a1 = 0, a2 = 0, a3 = 0;
        const ulonglong2* p0 = reinterpret_cast<const ulonglong2*>(&hcur[0][0]);
        const ulonglong2* p1 = reinterpret_cast<const ulonglong2*>(&hcur[1][0]);
        const ulonglong2* p2 = reinterpret_cast<const ulonglong2*>(&hcur[2][0]);
        const ulonglong2* p3 = reinterpret_cast<const ulonglong2*>(&hcur[3][0]);
#pragma unroll
        for (int q = 0; q < 16; ++q) {
            ulonglong2 v0 = p0[q], v1 = p1[q], v2 = p2[q], v3 = p3[q];
            fma2(a0, w2[2 * q], v0.x); fma2(a0, w2[2 * q + 1], v0.y);
            fma2(a1, w2[2 * q], v1.x); fma2(a1, w2[2 * q + 1], v1.y);
            fma2(a2, w2[2 * q], v2.x); fma2(a2, w2[2 * q + 1], v2.y);
            fma2(a3, w2[2 * q], v3.x); fma2(a3, w2[2 * q + 1], v3.y);
        }
        // prefetch next xw while sums settle
        float nxw = xw;
        if (tid < 256 && t + 1 < T_STEPS)
            nxw = g_xw[((size_t)(t + 1) * BATCH + b0 + fb) * HID + kb + fkj];
        {
            float x0, y0, x1, y1, x2, y2, x3, y3;
            unpack2(a0, x0, y0); unpack2(a1, x1, y1);
            unpack2(a2, x2, y2); unpack2(a3, x3, y3);
            const int pr = tid >> 6;   // destination peer (owner of jg)
            const int jl = tid & 63;   // local j within peer's slice
            stage[pr][0][jl] = x0 + y0;
            stage[pr][1][jl] = x1 + y1;
            stage[pr][2][jl] = x2 + y2;
            stage[pr][3][jl] = x3 + y3;
        }
        __syncthreads();   // staging complete; also: everyone done reading hcur

        // ---- send: 8 threads, one 1KB bulk each, tx into peer's full[wb] ----
        if (tid < 8) {
            asm volatile("fence.proxy.async.shared::cta;" ::: "memory");
            bulk_dsmem(remRecv + (unsigned)(wb * 8192) + mySlotOff,
                       stageL + peer * 1024u, 1024u, remMbar + (unsigned)(wb * 8));
        }

        // ---- wait for all 8 partial slices for THIS step ----
        mbar_wait(mbarL + wb * 8, par[wb]);
        par[wb] ^= 1;
        // re-arm this buffer's barrier for step t+2 (safe: same-phase tx commutes)
        if (tid == 0 && t + 2 < T_STEPS) mbar_expect_tx(mbarL + wb * 8, 8192);

        // ---- finalize: sum 8 partials, relu(+xw), write out + hcur ----
        if (tid < 256) {
            const float* rc = &recv[wb][0][fb][fkj];
            float s = rc[0 * 256] + rc[1 * 256] + rc[2 * 256] + rc[3 * 256]
                    + rc[4 * 256] + rc[5 * 256] + rc[6 * 256] + rc[7 * 256];
            float v = fmaxf(xw + s, 0.f);
            out[((size_t)t * BATCH + b0 + fb) * HID + kb + fkj] = v;
            hcur[fb][fkj] = v;
            if (t == T_STEPS - 1)
                out[(size_t)T_STEPS * BATCH * HID + (size_t)(b0 + fb) * HID + kb + fkj] = v;
        }
        xw = nxw;
        __syncthreads();   // hcur(t) visible before next GEMV
    }
    // keep smem alive until all peers' bulk traffic has fully drained
    CLUSTER_SYNC_ASM();
}

// ---------------- launch ----------------
extern "C" void kernel_launch(void* const* d_in, const int* in_sizes, int n_in,
                              void* d_out, int out_size)
{
    (void)in_sizes; (void)n_in; (void)out_size;
    const float* x   = (const float*)d_in[0];
    const float* wih = (const float*)d_in[1];
    const float* whh = (const float*)d_in[2];
    const float* bih = (const float*)d_in[3];
    const float* bhh = (const float*)d_in[4];
    float* out = (float*)d_out;

    dim3 g1((T_STEPS * BATCH) / BM, HID / BN);   // (256, 4)
    xw_gemm_kernel<<<g1, 256>>>(x, wih, bih, bhh);

    rnn_kernel<<<RNN_CTAS, RNN_THREADS>>>(whh, out);   // 128 CTAs, 16 clusters
}

// round 15
// speedup vs baseline: 1.8648x; 1.1467x over previous
#include <cuda_runtime.h>
#include <cstdint>

// Problem dims
#define T_STEPS 512
#define BATCH   64
#define INDIM   256
#define HID     512

// ---------------- f32x2 helpers (FFMA2 only reachable via PTX) ----------------
__device__ __forceinline__ unsigned long long pack2(float x, float y) {
    unsigned long long r;
    asm("mov.b64 %0, {%1,%2};" : "=l"(r) : "f"(x), "f"(y));
    return r;
}
__device__ __forceinline__ void unpack2(unsigned long long v, float& x, float& y) {
    asm("mov.b64 {%0,%1}, %2;" : "=f"(x), "=f"(y) : "l"(v));
}
__device__ __forceinline__ void fma2(unsigned long long& d, unsigned long long a,
                                     unsigned long long b) {
    asm("fma.rn.f32x2 %0, %1, %2, %0;" : "+l"(d) : "l"(a), "l"(b));
}

// ---------------- mbarrier / DSMEM helpers ----------------
__device__ __forceinline__ void mbar_init(unsigned addr, unsigned cnt) {
    asm volatile("mbarrier.init.shared.b64 [%0], %1;" :: "r"(addr), "r"(cnt) : "memory");
}
__device__ __forceinline__ void mbar_expect_tx(unsigned addr, unsigned bytes) {
    asm volatile("mbarrier.arrive.expect_tx.shared.b64 _, [%0], %1;"
                 :: "r"(addr), "r"(bytes) : "memory");
}
__device__ __forceinline__ void mbar_wait(unsigned addr, unsigned parity) {
    asm volatile(
        "{\n\t.reg .pred P;\n"
        "LW_%=:\n\t"
        "mbarrier.try_wait.parity.acquire.cluster.shared::cta.b64 P, [%0], %1, 0x989680;\n\t"
        "@P bra LD_%=;\n\t"
        "bra LW_%=;\n"
        "LD_%=:\n\t}"
        :: "r"(addr), "r"(parity) : "memory");
}
__device__ __forceinline__ unsigned mapa_sh(unsigned addr, unsigned rank) {
    unsigned r;
    asm("mapa.shared::cluster.u32 %0, %1, %2;" : "=r"(r) : "r"(addr), "r"(rank));
    return r;
}
// 1KB bulk DSMEM copy with tx-accounting into the DESTINATION CTA's mbarrier
__device__ __forceinline__ void bulk_dsmem(unsigned dst, unsigned src, unsigned bytes,
                                           unsigned dst_mbar) {
    asm volatile(
        "cp.async.bulk.shared::cluster.shared::cta.mbarrier::complete_tx::bytes "
        "[%0], [%1], %2, [%3];"
        :: "r"(dst), "r"(src), "r"(bytes), "r"(dst_mbar) : "memory");
}
#define CLUSTER_SYNC_ASM() do { \
    asm volatile("barrier.cluster.arrive.aligned;" ::: "memory"); \
    asm volatile("barrier.cluster.wait.aligned;" ::: "memory"); } while (0)

// ---------------- Phase 1: xw = x @ W_ih^T + bias_ih + bias_hh ----------------
__device__ float g_xw[(size_t)T_STEPS * BATCH * HID];   // 64 MB static scratch

#define BM 128
#define BN 128
#define BK 16
#define LDP 132

__global__ void __launch_bounds__(256, 2)
xw_gemm_kernel(const float* __restrict__ x, const float* __restrict__ wih,
               const float* __restrict__ bih, const float* __restrict__ bhh)
{
    __shared__ float As[BK * LDP];
    __shared__ float Bs[BK * LDP];

    const int tid = threadIdx.x;
    const int mb = blockIdx.x * BM;
    const int nb = blockIdx.y * BN;

    const int tx = tid & 15;
    const int ty = tid >> 4;
    const int m0 = ty * 8;
    const int n0 = tx * 8;

    const int lrow = tid >> 2;
    const int lk   = (tid & 3) * 4;

    unsigned long long acc2[4][8];
#pragma unroll
    for (int i = 0; i < 4; ++i)
#pragma unroll
        for (int n = 0; n < 8; ++n) acc2[i][n] = 0ull;

    for (int k0 = 0; k0 < INDIM; k0 += BK) {
#pragma unroll
        for (int h = 0; h < 2; ++h) {
            const int row = lrow + h * 64;
            float4 a = *reinterpret_cast<const float4*>(x + (size_t)(mb + row) * INDIM + k0 + lk);
            As[(lk + 0) * LDP + row] = a.x;
            As[(lk + 1) * LDP + row] = a.y;
            As[(lk + 2) * LDP + row] = a.z;
            As[(lk + 3) * LDP + row] = a.w;
            float4 b = *reinterpret_cast<const float4*>(wih + (size_t)(nb + row) * INDIM + k0 + lk);
            Bs[(lk + 0) * LDP + row] = b.x;
            Bs[(lk + 1) * LDP + row] = b.y;
            Bs[(lk + 2) * LDP + row] = b.z;
            Bs[(lk + 3) * LDP + row] = b.w;
        }
        __syncthreads();

#pragma unroll
        for (int k = 0; k < BK; ++k) {
            const ulonglong2* ap = reinterpret_cast<const ulonglong2*>(As + k * LDP + m0);
            ulonglong2 am0 = ap[0];
            ulonglong2 am1 = ap[1];
            unsigned long long av[4] = {am0.x, am0.y, am1.x, am1.y};
            float4 b0 = *reinterpret_cast<const float4*>(Bs + k * LDP + n0);
            float4 b1 = *reinterpret_cast<const float4*>(Bs + k * LDP + n0 + 4);
            unsigned long long bb[8] = {
                pack2(b0.x, b0.x), pack2(b0.y, b0.y), pack2(b0.z, b0.z), pack2(b0.w, b0.w),
                pack2(b1.x, b1.x), pack2(b1.y, b1.y), pack2(b1.z, b1.z), pack2(b1.w, b1.w)};
#pragma unroll
            for (int i = 0; i < 4; ++i)
#pragma unroll
                for (int n = 0; n < 8; ++n)
                    fma2(acc2[i][n], av[i], bb[n]);
        }
        __syncthreads();
    }

    float bia[8];
#pragma unroll
    for (int n = 0; n < 8; ++n)
        bia[n] = __ldg(bih + nb + n0 + n) + __ldg(bhh + nb + n0 + n);

#pragma unroll
    for (int i = 0; i < 4; ++i) {
        float lo[8], hi[8];
#pragma unroll
        for (int n = 0; n < 8; ++n) unpack2(acc2[i][n], lo[n], hi[n]);
        float* dst0 = g_xw + (size_t)(mb + m0 + 2 * i) * HID + nb + n0;
        float* dst1 = dst0 + HID;
        float4 o;
        o.x = lo[0] + bia[0]; o.y = lo[1] + bia[1]; o.z = lo[2] + bia[2]; o.w = lo[3] + bia[3];
        *reinterpret_cast<float4*>(dst0) = o;
        o.x = lo[4] + bia[4]; o.y = lo[5] + bia[5]; o.z = lo[6] + bia[6]; o.w = lo[7] + bia[7];
        *reinterpret_cast<float4*>(dst0 + 4) = o;
        o.x = hi[0] + bia[0]; o.y = hi[1] + bia[1]; o.z = hi[2] + bia[2]; o.w = hi[3] + bia[3];
        *reinterpret_cast<float4*>(dst1) = o;
        o.x = hi[4] + bia[4]; o.y = hi[5] + bia[5]; o.z = hi[6] + bia[6]; o.w = hi[7] + bia[7];
        *reinterpret_cast<float4*>(dst1 + 4) = o;
    }
}

// ---------------- Phase 2: recurrence (k-partitioned reduce-scatter) ----------------
// 16 clusters x 8 CTAs, 256 threads/CTA (2 j per thread -> 255-reg budget, LDS halved).
// CTA rank r owns k-slice AND j-slice [64r, 64r+64).
//   GEMV: thread tid computes partials for j1=tid and j2=tid+256 over k in Kr,
//         reading only LOCAL hcur; W rows in regs (64 u64/thread), h loads shared by j1/j2.
//   Exchange: 7 remote 1KB cp.async.bulk (own slice copied locally, no self-send),
//         tx-counted into peer's full[wb] mbarrier (expects 7*1024B).
//   Finalize: thread tid (exactly 256 slots) sums 8 partial slices, relu(+xw).
// Double buffering + 2-step dependency chain gives WAR ordering: no empty barrier.

#define CL_SIZE     8
#define RNN_THREADS 256
#define RNN_CTAS    128          // 16 clusters * 8

__global__ void __launch_bounds__(RNN_THREADS, 1) __cluster_dims__(CL_SIZE, 1, 1)
rnn_kernel(const float* __restrict__ whh, float* __restrict__ out)
{
    __shared__ alignas(16) float hcur[4][64];             // 1KB  local h slice
    __shared__ alignas(16) float stage[CL_SIZE][4][64];   // 8KB  outgoing partials
    __shared__ alignas(16) float recv[2][CL_SIZE][4][64]; // 16KB incoming (dbl buf)
    __shared__ alignas(8)  unsigned long long mbar[2];    // full[0], full[1]

    const int tid  = threadIdx.x;
    const int rank = blockIdx.x & (CL_SIZE - 1);
    const int cl   = blockIdx.x >> 3;
    const int b0   = cl * 4;
    const int kb   = rank * 64;      // our k-slice base
    const int jl   = tid & 63;       // local j within a 64-slice

    // W rows for j1 = tid (peer tid>>6) and j2 = tid+256 (peer 4+(tid>>6)),
    // k in [kb, kb+64) -> 2 x 32 packed u64, register-resident (128 regs)
    unsigned long long w2[64];
    {
        const unsigned long long* r0 =
            reinterpret_cast<const unsigned long long*>(whh + (size_t)tid * HID + kb);
        const unsigned long long* r1 =
            reinterpret_cast<const unsigned long long*>(whh + (size_t)(tid + 256) * HID + kb);
#pragma unroll
        for (int i = 0; i < 32; ++i) { w2[i] = r0[i]; w2[32 + i] = r1[i]; }
    }

    // h(-1) = 0
    (&hcur[0][0])[tid] = 0.f;

    const unsigned mbarL  = (unsigned)__cvta_generic_to_shared(mbar);
    const unsigned recvL  = (unsigned)__cvta_generic_to_shared(&recv[0][0][0][0]);
    const unsigned stageL = (unsigned)__cvta_generic_to_shared(&stage[0][0][0]);

    if (tid == 0) {
        mbar_init(mbarL + 0, 1);
        mbar_init(mbarL + 8, 1);
        mbar_expect_tx(mbarL + 0, 7168);   // phase for step 0 (7 remote slices)
        mbar_expect_tx(mbarL + 8, 7168);   // phase for step 1
    }

    // bulk issuers: tid 0..6 -> peer skipping own rank
    const unsigned peer      = (unsigned)(tid + (tid >= rank ? 1 : 0)) & 7u;
    const unsigned remRecv   = mapa_sh(recvL, peer);
    const unsigned remMbar   = mapa_sh(mbarL, peer);
    const unsigned mySlotOff = (unsigned)(rank * 1024);

    // finalize indices: thread tid -> (batch fb, local j fkj) of OWN slice
    const int fb  = tid >> 6;
    const int fkj = jl;
    float xw = g_xw[(size_t)(b0 + fb) * HID + kb + fkj];

    __syncthreads();
    CLUSTER_SYNC_ASM();   // mbarrier inits + expects visible cluster-wide

    int par[2] = {0, 0};

    for (int t = 0; t < T_STEPS; ++t) {
        const int wb = t & 1;

        // ---- GEMV: partials for j1=tid, j2=tid+256 over k in [kb,kb+64) ----
        unsigned long long acc[8];   // [0..3]=j1 b0..b3, [4..7]=j2 b0..b3
#pragma unroll
        for (int i = 0; i < 8; ++i) acc[i] = 0ull;
        const ulonglong2* p0 = reinterpret_cast<const ulonglong2*>(&hcur[0][0]);
        const ulonglong2* p1 = reinterpret_cast<const ulonglong2*>(&hcur[1][0]);
        const ulonglong2* p2 = reinterpret_cast<const ulonglong2*>(&hcur[2][0]);
        const ulonglong2* p3 = reinterpret_cast<const ulonglong2*>(&hcur[3][0]);
#pragma unroll
        for (int q = 0; q < 16; ++q) {
            ulonglong2 v0 = p0[q], v1 = p1[q], v2 = p2[q], v3 = p3[q];
            unsigned long long wa0 = w2[2 * q], wa1 = w2[2 * q + 1];
            unsigned long long wb0 = w2[32 + 2 * q], wb1 = w2[32 + 2 * q + 1];
            fma2(acc[0], wa0, v0.x); fma2(acc[0], wa1, v0.y);
            fma2(acc[1], wa0, v1.x); fma2(acc[1], wa1, v1.y);
            fma2(acc[2], wa0, v2.x); fma2(acc[2], wa1, v2.y);
            fma2(acc[3], wa0, v3.x); fma2(acc[3], wa1, v3.y);
            fma2(acc[4], wb0, v0.x); fma2(acc[4], wb1, v0.y);
            fma2(acc[5], wb0, v1.x); fma2(acc[5], wb1, v1.y);
            fma2(acc[6], wb0, v2.x); fma2(acc[6], wb1, v2.y);
            fma2(acc[7], wb0, v3.x); fma2(acc[7], wb1, v3.y);
        }
        // prefetch next xw (independent)
        float nxw = xw;
        if (t + 1 < T_STEPS)
            nxw = g_xw[((size_t)(t + 1) * BATCH + b0 + fb) * HID + kb + fkj];
        {
            const int pr1 = tid >> 6;        // peer owning j1
            const int pr2 = 4 + (tid >> 6);  // peer owning j2
            float x0, y0;
#pragma unroll
            for (int b = 0; b < 4; ++b) {
                unpack2(acc[b], x0, y0);     stage[pr1][b][jl] = x0 + y0;
                unpack2(acc[4 + b], x0, y0); stage[pr2][b][jl] = x0 + y0;
            }
        }
        __syncthreads();   // staging complete; everyone done reading hcur

        // ---- send: 7 threads, one 1KB bulk each (no self-send) ----
        if (tid < 7) {
            asm volatile("fence.proxy.async.shared::cta;" ::: "memory");
            bulk_dsmem(remRecv + (unsigned)(wb * 8192) + mySlotOff,
                       stageL + peer * 1024u, 1024u, remMbar + (unsigned)(wb * 8));
        }

        // ---- own slice: stage[rank] -> recv[wb][rank] locally (1 float/thread) ----
        // finalize thread tid reads exactly the slot it writes -> no extra sync
        recv[wb][rank][fb][fkj] = stage[rank][fb][fkj];

        // ---- wait for 7 remote slices ----
        mbar_wait(mbarL + wb * 8, par[wb]);
        par[wb] ^= 1;
        if (tid == 0 && t + 2 < T_STEPS) mbar_expect_tx(mbarL + wb * 8, 7168);

        // ---- finalize: sum 8 partials, relu(+xw), write out + hcur ----
        {
            const float* rc = &recv[wb][0][fb][fkj];
            float s = rc[0 * 256] + rc[1 * 256] + rc[2 * 256] + rc[3 * 256]
                    + rc[4 * 256] + rc[5 * 256] + rc[6 * 256] + rc[7 * 256];
            float v = fmaxf(xw + s, 0.f);
            out[((size_t)t * BATCH + b0 + fb) * HID + kb + fkj] = v;
            hcur[fb][fkj] = v;
            if (t == T_STEPS - 1)
                out[(size_t)T_STEPS * BATCH * HID + (size_t)(b0 + fb) * HID + kb + fkj] = v;
        }
        xw = nxw;
        __syncthreads();   // hcur(t) visible before next GEMV
    }
    // keep smem alive until all peers' bulk traffic has drained
    CLUSTER_SYNC_ASM();
}

// ---------------- launch ----------------
extern "C" void kernel_launch(void* const* d_in, const int* in_sizes, int n_in,
                              void* d_out, int out_size)
{
    (void)in_sizes; (void)n_in; (void)out_size;
    const float* x   = (const float*)d_in[0];
    const float* wih = (const float*)d_in[1];
    const float* whh = (const float*)d_in[2];
    const float* bih = (const float*)d_in[3];
    const float* bhh = (const float*)d_in[4];
    float* out = (float*)d_out;

    dim3 g1((T_STEPS * BATCH) / BM, HID / BN);   // (256, 4)
    xw_gemm_kernel<<<g1, 256>>>(x, wih, bih, bhh);

    rnn_kernel<<<RNN_CTAS, RNN_THREADS>>>(whh, out);   // 128 CTAs, 16 clusters
}